// round 8
// baseline (speedup 1.0000x reference)
#include <cuda_runtime.h>

// Problem constants
#define BB   64
#define NN   883
#define NPAD 912    // NN padded to multiple of TM (19*48)
#define EE   10
#define CINx 66     // DIN + DOUT
#define DO   64     // DOUT
#define OG   128    // gate output width (2*DOUT)
#define OU   64     // update output width

// L@x tiling
#define TN   128
#define TM   48
#define DXROW 180   // dup'd dxs row: 9 chunks x 20 floats (16 data + 4 pad)
#define LXT  160    // threads: phase1 uses 128, phase2 uses 144

typedef unsigned long long ull;

// ---------------- scratch (device globals; no allocation allowed) ----------------
__device__ __align__(16) float g_Wg[NN * 2 * CINx * OG];   // per-node gate weights
__device__ __align__(16) float g_bg[NN * OG];
__device__ __align__(16) float g_Wu[NN * 2 * CINx * OU];   // per-node update weights
__device__ __align__(16) float g_bu[NN * OU];
__device__ float g_xs[BB * NN * CINx];       // current DGCN input (concat)
__device__ __align__(16) float g_nv[BB * NPAD * EE];    // nodevec (padded, zero tail)
__device__ float g_d[BB * NN];               // degree^-0.5
__device__ __align__(16) float g_dxs2[BB * NPAD * DXROW]; // dup'd d*xs (42 MB)
__device__ float g_y2[BB * NN * CINx];       // L @ xs
__device__ float g_zr[BB * NN * OG];         // sigmoid(gate out): z | r

__device__ __forceinline__ float sigm(float v) { return 1.f / (1.f + expf(-v)); }

__device__ __forceinline__ ull pk2(float a, float b) {
    ull r; asm("mov.b64 %0, {%1, %2};" : "=l"(r) : "f"(a), "f"(b)); return r;
}
__device__ __forceinline__ ull fma2(ull a, ull b, ull c) {
    ull d; asm("fma.rn.f32x2 %0, %1, %2, %3;" : "=l"(d) : "l"(a), "l"(b), "l"(c)); return d;
}
__device__ __forceinline__ float2 upk(ull v) {
    float2 f; asm("mov.b64 {%0, %1}, %2;" : "=f"(f.x), "=f"(f.y) : "l"(v)); return f;
}

// ---------------- per-node weight pools (float4 vectorized) ----------------
__global__ void k_genw4(const float* __restrict__ emb, const float* __restrict__ pool,
                        float* __restrict__ outw, int J4) {
    int n = blockIdx.y;
    int j = blockIdx.x * blockDim.x + threadIdx.x;
    if (j >= J4) return;
    const float4* p4 = (const float4*)pool;
    float4 acc = make_float4(0.f, 0.f, 0.f, 0.f);
#pragma unroll
    for (int e = 0; e < EE; e++) {
        float w = emb[n * EE + e];
        float4 p = p4[e * J4 + j];
        acc.x += w * p.x; acc.y += w * p.y; acc.z += w * p.z; acc.w += w * p.w;
    }
    ((float4*)outw)[n * J4 + j] = acc;
}

// ---------------- build xs, hyper-net filter, nodevec (padded rows zeroed) --------
__global__ void k_prep(const float* __restrict__ x, const float* __restrict__ state,
                       const float* __restrict__ emb, const float* __restrict__ tim,
                       const float* __restrict__ day, const float* __restrict__ spd,
                       const float* __restrict__ occ,
                       const float* __restrict__ w1, const float* __restrict__ b1,
                       const float* __restrict__ w2, const float* __restrict__ b2,
                       const float* __restrict__ w3, const float* __restrict__ b3,
                       int is_update) {
    int idx = blockIdx.x * blockDim.x + threadIdx.x;   // over BB*NPAD
    if (idx >= BB * NPAD) return;
    int n = idx % NPAD;
    int b = idx / NPAD;
    float* nvp = g_nv + idx * EE;
    if (n >= NN) {                    // zero padded tail rows
#pragma unroll
        for (int e = 0; e < EE; e++) nvp[e] = 0.f;
        return;
    }
    int bn = b * NN + n;

    float c[CINx];
    c[0] = x[bn * 2 + 0];
    c[1] = x[bn * 2 + 1];
    const float* st = state + bn * DO;
    if (is_update) {
        const float* z = g_zr + bn * OG;   // z = zr[..., :64]
#pragma unroll
        for (int j = 0; j < DO; j++) c[2 + j] = z[j] * st[j];
    } else {
#pragma unroll
        for (int j = 0; j < DO; j++) c[2 + j] = st[j];
    }
    float* xo = g_xs + bn * CINx;
#pragma unroll
    for (int i = 0; i < CINx; i++) xo[i] = c[i];

    // fc1 (66->16) sigmoid
    float h1[16];
#pragma unroll
    for (int t = 0; t < 16; t++) h1[t] = b1[t];
    for (int i = 0; i < CINx; i++) {
        float ci = c[i];
#pragma unroll
        for (int t = 0; t < 16; t++) h1[t] += ci * w1[i * 16 + t];
    }
#pragma unroll
    for (int t = 0; t < 16; t++) h1[t] = sigm(h1[t]);

    // fc2 (16->2) sigmoid
    float h2[2];
#pragma unroll
    for (int u = 0; u < 2; u++) {
        float s = b2[u];
#pragma unroll
        for (int t = 0; t < 16; t++) s += h1[t] * w2[t * 2 + u];
        h2[u] = sigm(s);
    }

    // fc3 (2->10); dyn modulated embedding; nodevec = tanh
#pragma unroll
    for (int e = 0; e < EE; e++) {
        float f = b3[e] + h2[0] * w3[e] + h2[1] * w3[EE + e];
        float dyn = emb[n * EE + e] * tim[bn * EE + e] * day[bn * EE + e]
                  * spd[bn * EE + e] * occ[bn * EE + e];
        nvp[e] = tanhf(dyn * f);
    }
}

// ---------------- d[b,n] = rsqrt( sum_m relu(nv_n . nv_m) ) ------------------------
__global__ void k_degree() {
    __shared__ __align__(16) float s_nv[NN * EE];   // 35.3 KB
    int b = blockIdx.y;
    const float* nvb = g_nv + b * NPAD * EE;
    for (int i = threadIdx.x; i < NN * EE; i += blockDim.x) s_nv[i] = nvb[i];
    __syncthreads();
    int n = blockIdx.x * blockDim.x + threadIdx.x;
    if (n >= NN) return;
    ull my[5];
    const ull* myp = (const ull*)(s_nv + n * EE);
#pragma unroll
    for (int e = 0; e < 5; e++) my[e] = myp[e];
    float sum = 0.f;
#pragma unroll 2
    for (int m = 0; m < NN; m++) {
        const ull* row = (const ull*)(s_nv + m * EE);
        ull d2 = 0ull;
#pragma unroll
        for (int e = 0; e < 5; e++) d2 = fma2(my[e], row[e], d2);
        float2 f = upk(d2);
        sum += fmaxf(f.x + f.y, 0.f);
    }
    g_d[b * NN + n] = rsqrtf(sum);
}

// ---------------- dxs2: duplicated (v,v) pairs, 20-float padded chunks -------------
// grid (NPAD/8, BB), block (45, 8). float4 #f4 of a row: chunk cg=f4/5, j=f4%5.
// j<4: (v_c0,v_c0,v_c0+1,v_c0+1) with c0 = cg*8 + 2j; j==4: pad zeros.
__global__ void k_scale() {
    int b = blockIdx.y;
    int m = blockIdx.x * 8 + threadIdx.y;
    int f4 = threadIdx.x;                 // 0..44
    int cg = f4 / 5, j = f4 % 5;
    float4 v = make_float4(0.f, 0.f, 0.f, 0.f);
    if (m < NN && j < 4) {
        float dm = g_d[b * NN + m];
        const float* xr = g_xs + (b * NN + m) * CINx;
        int c0 = cg * 8 + j * 2;
        if (c0 < CINx)     { float t = dm * xr[c0];     v.x = t; v.y = t; }
        if (c0 + 1 < CINx) { float t = dm * xr[c0 + 1]; v.z = t; v.w = t; }
    }
    ((float4*)g_dxs2)[(b * NPAD + m) * (DXROW / 4) + f4] = v;
}

// ---------------- y2 = xs - d_n * (relu(NV NV^T) @ (d*xs)) -------------------------
// Phase 1: thread (tid<128) = one row n, nodevec in regs -> s_a[mm][n].
// Phase 2: thread (tid<144) = (rg: 8 rows, cg: 8 channels). FFMA2 packed over
// n-PAIRS: a-pairs direct LDS from s_a (consecutive n), v pre-duplicated in s_dx2.
__global__ void __launch_bounds__(LXT, 3) k_lx() {
    extern __shared__ __align__(16) float smem[];
    float* s_dx2 = smem;                      // TM * DXROW = 8640 floats (34.6 KB)
    float* s_a   = smem + TM * DXROW;         // TM * TN    = 6144 floats (24.6 KB)
    float* s_nvm = s_a + TM * TN;             // TM * EE    = 480 floats

    int b = blockIdx.y;
    int n0 = blockIdx.x * TN;
    int tid = threadIdx.x;
    const float* nvb = g_nv + b * NPAD * EE;

    // phase-1 row nodevec in registers (packed)
    ull nvr[5];
    {
        int n = n0 + ((tid < TN) ? tid : 0);
        const ull* p = (const ull*)(nvb + n * EE);
#pragma unroll
        for (int e = 0; e < 5; e++) nvr[e] = p[e];
    }

    int rg = tid / 9;     // 0..15 (8 rows each)
    int cg = tid % 9;     // 0..8  (8 channels each)
    bool p2 = tid < 144;

    // acc2[c][np] = packed (row 2np, row 2np+1) accumulators for channel cg*8+c
    ull acc2[8][4];
#pragma unroll
    for (int c = 0; c < 8; c++)
#pragma unroll
        for (int t = 0; t < 4; t++) acc2[c][t] = 0ull;

    for (int mt = 0; mt < NPAD; mt += TM) {
        __syncthreads();   // protect smem reuse
        {
            const float4* gn = (const float4*)(nvb + mt * EE);
            float4* sn = (float4*)s_nvm;
            for (int i = tid; i < TM * EE / 4; i += LXT) sn[i] = gn[i];
            const float4* gd = (const float4*)g_dxs2 + (b * NPAD + mt) * (DXROW / 4);
            float4* sd = (float4*)s_dx2;
#pragma unroll 2
            for (int i = tid; i < TM * DXROW / 4; i += LXT) sd[i] = gd[i];
        }
        __syncthreads();

        // phase 1: A[mm][tid]
        if (tid < TN) {
#pragma unroll 2
            for (int mm = 0; mm < TM; mm++) {
                const ull* q = (const ull*)(s_nvm + mm * EE);
                ull d2 = 0ull;
#pragma unroll
                for (int e = 0; e < 5; e++) d2 = fma2(nvr[e], q[e], d2);
                float2 f = upk(d2);
                s_a[mm * TN + tid] = fmaxf(f.x + f.y, 0.f);
            }
        }
        __syncthreads();

        // phase 2: n-pair packed outer product, zero MOV duplication
        if (p2) {
#pragma unroll 2
            for (int mm = 0; mm < TM; mm++) {
                const ulonglong2* ap = (const ulonglong2*)(s_a + mm * TN + rg * 8);
                ulonglong2 A0 = ap[0];            // pairs (r0,r1),(r2,r3)
                ulonglong2 A1 = ap[1];            // pairs (r4,r5),(r6,r7)
                const float* vp = s_dx2 + mm * DXROW + cg * 20;
                ulonglong2 V0 = *(const ulonglong2*)(vp);       // dup c0,c1
                ulonglong2 V1 = *(const ulonglong2*)(vp + 4);   // dup c2,c3
                ulonglong2 V2 = *(const ulonglong2*)(vp + 8);   // dup c4,c5
                ulonglong2 V3 = *(const ulonglong2*)(vp + 12);  // dup c6,c7
                ull vd[8] = {V0.x, V0.y, V1.x, V1.y, V2.x, V2.y, V3.x, V3.y};
                ull ad[4] = {A0.x, A0.y, A1.x, A1.y};
#pragma unroll
                for (int c = 0; c < 8; c++) {
#pragma unroll
                    for (int t = 0; t < 4; t++)
                        acc2[c][t] = fma2(vd[c], ad[t], acc2[c][t]);
                }
            }
        }
    }

    if (p2) {
#pragma unroll
        for (int q = 0; q < 8; q++) {
            int n = n0 + rg * 8 + q;
            if (n >= NN) continue;
            float dn = g_d[b * NN + n];
            int base = (b * NN + n) * CINx;
            int c0 = cg * 8;
#pragma unroll
            for (int c = 0; c < 8; c++) {
                int cc = c0 + c;
                if (cc < CINx) {
                    float2 f = upk(acc2[c][q >> 1]);
                    float val = (q & 1) ? f.y : f.x;
                    g_y2[base + cc] = g_xs[base + cc] - dn * val;
                }
            }
        }
    }
}

// ---------------- out[b,n,o] = sum_ki xg[b,n,k,i] W[n,k,i,o] + bias ----------------
__global__ void k_out(const float* __restrict__ W, const float* __restrict__ bias,
                      const float* __restrict__ state, int Ot, int mode,
                      float* __restrict__ outp) {
    __shared__ __align__(16) float sW[2 * CINx * 64];   // W[n,:,:, og*64..+63]
    __shared__ __align__(16) float sf[132 * 16];        // 16 batches, swizzled

    int n  = blockIdx.y;
    int og = blockIdx.x;
    int tid = threadIdx.x;
    int ol  = tid & 63;     // local o
    int grp = tid >> 6;     // 0/1

    {
        const float4* W4 = (const float4*)(W + n * 132 * Ot + og * 64);
        int ot4 = Ot >> 2;
        float4* sW4 = (float4*)sW;
        for (int idx = tid; idx < 132 * 16; idx += 128) {
            int iki = idx >> 4, o4 = idx & 15;
            sW4[iki * 16 + o4] = W4[iki * ot4 + o4];
        }
    }
    float bval = bias[n * Ot + og * 64 + ol];

    for (int bt = 0; bt < 4; bt++) {      // 4 chunks of 16 batches
        __syncthreads();
        for (int idx = tid; idx < 16 * 132; idx += 128) {
            int bb = idx / 132, ii = idx % 132;
            int base = ((bt * 16 + bb) * NN + n) * CINx;
            float v = (ii < CINx) ? g_xs[base + ii] : g_y2[base + ii - CINx];
            int w = ii * 16 + ((((bb >> 2) ^ (ii & 3)) << 2) | (bb & 3));
            sf[w] = v;
        }
        __syncthreads();

        ull acc[4];
#pragma unroll
        for (int k = 0; k < 4; k++) acc[k] = pk2(bval, bval);

        for (int ii = 0; ii < 132; ii++) {
            float w = sW[ii * 64 + ol];
            ull wp = pk2(w, w);
            const ulonglong2* p = (const ulonglong2*)(sf + ii * 16);
            ulonglong2 v0 = p[(2 * grp) ^ (ii & 3)];
            ulonglong2 v1 = p[(2 * grp + 1) ^ (ii & 3)];
            acc[0] = fma2(wp, v0.x, acc[0]);
            acc[1] = fma2(wp, v0.y, acc[1]);
            acc[2] = fma2(wp, v1.x, acc[2]);
            acc[3] = fma2(wp, v1.y, acc[3]);
        }

#pragma unroll
        for (int k = 0; k < 4; k++) {
            float2 f = upk(acc[k]);
            float vv[2] = {f.x, f.y};
#pragma unroll
            for (int h = 0; h < 2; h++) {
                int b = bt * 16 + grp * 8 + k * 2 + h;
                if (mode == 0) {
                    g_zr[(b * NN + n) * OG + og * 64 + ol] = sigm(vv[h]);
                } else {
                    float hc = tanhf(vv[h]);
                    float r  = g_zr[(b * NN + n) * OG + 64 + ol];
                    float st = state[(b * NN + n) * DO + ol];
                    outp[(b * NN + n) * DO + ol] = r * st + (1.f - r) * hc;
                }
            }
        }
    }
}

// ---------------- launch ----------------
#define SMEM_LX ((TM * DXROW + TM * TN + TM * EE) * 4)

extern "C" void kernel_launch(void* const* d_in, const int* in_sizes, int n_in,
                              void* d_out, int out_size) {
    const float* x     = (const float*)d_in[0];
    const float* state = (const float*)d_in[1];
    const float* emb   = (const float*)d_in[2];
    const float* tim   = (const float*)d_in[3];
    const float* day   = (const float*)d_in[4];
    const float* spd   = (const float*)d_in[5];
    const float* occ   = (const float*)d_in[6];
    const float* gwp   = (const float*)d_in[7];
    const float* gbp   = (const float*)d_in[8];
    const float* g1w = (const float*)d_in[9],  *g1b = (const float*)d_in[10];
    const float* g2w = (const float*)d_in[11], *g2b = (const float*)d_in[12];
    const float* g3w = (const float*)d_in[13], *g3b = (const float*)d_in[14];
    const float* uwp = (const float*)d_in[15], *ubp = (const float*)d_in[16];
    const float* u1w = (const float*)d_in[17], *u1b = (const float*)d_in[18];
    const float* u2w = (const float*)d_in[19], *u2b = (const float*)d_in[20];
    const float* u3w = (const float*)d_in[21], *u3b = (const float*)d_in[22];
    float* out = (float*)d_out;

    float *pWg, *pbg, *pWu, *pbu;
    cudaGetSymbolAddress((void**)&pWg, g_Wg);
    cudaGetSymbolAddress((void**)&pbg, g_bg);
    cudaGetSymbolAddress((void**)&pWu, g_Wu);
    cudaGetSymbolAddress((void**)&pbu, g_bu);

    static int smem_set = 0;
    if (!smem_set) {
        cudaFuncSetAttribute(k_lx, cudaFuncAttributeMaxDynamicSharedMemorySize, SMEM_LX);
        smem_set = 1;
    }

    int npr = BB * NPAD;

    // --- gate DGCN ---
    k_prep<<<(npr + 127) / 128, 128>>>(x, state, emb, tim, day, spd, occ,          // 1
                                       g1w, g1b, g2w, g2b, g3w, g3b, 0);
    k_degree<<<dim3(2, BB), 512>>>();                                              // 2
    k_scale<<<dim3(NPAD / 8, BB), dim3(45, 8)>>>();                                // 3
    k_lx<<<dim3((NN + TN - 1) / TN, BB), LXT, SMEM_LX>>>();                        // 4 <- ncu
    k_genw4<<<dim3((2 * CINx * OG / 4 + 127) / 128, NN), 128>>>(emb, gwp, pWg,     // 5
                                                                2 * CINx * OG / 4);
    k_genw4<<<dim3(1, NN), 128>>>(emb, gbp, pbg, OG / 4);                          // 6
    k_out<<<dim3(2, NN), 128>>>(pWg, pbg, state, OG, 0, nullptr);                  // 7

    // --- update DGCN (cand input = [x, z*state]) + GRU epilogue ---
    k_prep<<<(npr + 127) / 128, 128>>>(x, state, emb, tim, day, spd, occ,          // 8
                                       u1w, u1b, u2w, u2b, u3w, u3b, 1);
    k_degree<<<dim3(2, BB), 512>>>();                                              // 9
    k_scale<<<dim3(NPAD / 8, BB), dim3(45, 8)>>>();                                // 10
    k_lx<<<dim3((NN + TN - 1) / TN, BB), LXT, SMEM_LX>>>();                        // 11
    k_genw4<<<dim3((2 * CINx * OU / 4 + 127) / 128, NN), 128>>>(emb, uwp, pWu,     // 12
                                                                2 * CINx * OU / 4);
    k_genw4<<<dim3(1, NN), 128>>>(emb, ubp, pbu, OU / 4);                          // 13
    k_out<<<dim3(1, NN), 128>>>(pWu, pbu, state, OU, 1, out);                      // 14
}